// round 15
// baseline (speedup 1.0000x reference)
#include <cuda_runtime.h>
#include <cuda_fp16.h>
#include <cstdint>

// ---------------- problem constants ----------------
#define N_NODES 100000
#define N_EDGES 3200000
#define F_IN    512
#define HEADS   8
#define HID     8
#define C1      64
#define NCLS    16
#define TOTE    (N_EDGES + N_NODES)
#define NB1024  ((N_NODES + 1023) / 1024)

// ---------------- device scratch ----------------
__device__ __half g_h1  [(size_t)N_NODES * C1];
__device__ float  g_hact[(size_t)N_NODES * C1];
__device__ float  g_as1 [(size_t)N_NODES * HEADS];
__device__ float  g_ad1 [(size_t)N_NODES * HEADS];
__device__ __half g_h2  [(size_t)N_NODES * NCLS];
__device__ float  g_as2 [N_NODES];
__device__ float  g_ad2 [N_NODES];
__device__ int    g_rowptr[N_NODES + 1];
__device__ int    g_cnt [N_NODES];
__device__ int    g_woff[N_NODES];
__device__ int    g_srcs[TOTE];
__device__ int    g_part [128];
__device__ int    g_part2[128];
__device__ int    g_is64;
__device__ unsigned g_gmax1[8];
__device__ unsigned g_gmax2;

// ---------------- helpers ----------------
__device__ __forceinline__ float leaky02(float x) { return fmaxf(x, 0.2f * x); }

__device__ __forceinline__ unsigned long long pack2(float x, float y) {
    unsigned long long r;
    asm("mov.b64 %0,{%1,%2};" : "=l"(r) : "f"(x), "f"(y));
    return r;
}
__device__ __forceinline__ void fma2(unsigned long long& d, unsigned long long a, unsigned long long b) {
    asm("fma.rn.f32x2 %0,%1,%2,%0;" : "+l"(d) : "l"(a), "l"(b));
}
__device__ __forceinline__ float2 unpack2(unsigned long long v) {
    float2 f;
    asm("mov.b64 {%0,%1},%2;" : "=f"(f.x), "=f"(f.y) : "l"(v));
    return f;
}
__device__ __forceinline__ unsigned fenc(float f) {
    unsigned u = __float_as_uint(f);
    return (u & 0x80000000u) ? ~u : (u | 0x80000000u);
}
__device__ __forceinline__ float fdec(unsigned u) {
    return __uint_as_float((u & 0x80000000u) ? (u & 0x7FFFFFFFu) : ~u);
}
#define ENC_NEG_INF 0x007FFFFFu

// ---------------- dtype probe + per-call resets ----------------
__global__ void probe_k(const void* ei) {
    __shared__ int s_bad;
    if (threadIdx.x < 8)  g_gmax1[threadIdx.x] = ENC_NEG_INF;
    if (threadIdx.x == 8) g_gmax2 = ENC_NEG_INF;
    if (threadIdx.x == 0) s_bad = 0;
    __syncthreads();
    const long long* p = (const long long*)ei;
    for (int i = threadIdx.x; i < 1024; i += blockDim.x) {
        long long v = p[i];
        if ((v >> 32) != 0) s_bad = 1;
    }
    __syncthreads();
    if (threadIdx.x == 0) g_is64 = (s_bad == 0) ? 1 : 0;
}

// ---------------- GEMM1 + fused attn coefs + fused head-max ----------------
#define MT 256
#define BK 16

__device__ __forceinline__ void g1_load(const float* __restrict__ X, int m0, int k0,
                                        int lrow0, int lh, const float* __restrict__ W,
                                        int tid, float4 ra[2][2], float4& rb) {
#pragma unroll
    for (int s = 0; s < 2; s++) {
        int row = lrow0 + s * 128;
        int gm  = m0 + row;
        if (gm < N_NODES) {
            const float4* p = (const float4*)(X + (size_t)gm * F_IN + k0 + lh);
            ra[s][0] = p[0];
            ra[s][1] = p[1];
        } else {
            ra[s][0] = make_float4(0.f, 0.f, 0.f, 0.f);
            ra[s][1] = make_float4(0.f, 0.f, 0.f, 0.f);
        }
    }
    rb = *(const float4*)(W + (size_t)(k0 + (tid >> 4)) * 64 + (tid & 15) * 4);
}

__device__ __forceinline__ void g1_store(float As[BK][MT], float Bs[BK][64],
                                         int lrow0, int lh, int tid,
                                         const float4 ra[2][2], const float4& rb) {
#pragma unroll
    for (int s = 0; s < 2; s++) {
        int row = lrow0 + s * 128;
        const float* f = (const float*)&ra[s][0];
#pragma unroll
        for (int j = 0; j < 8; j++) {
            int k = lh + j;
            As[k][row ^ ((2 * k) & 31)] = f[j];
        }
    }
    *(float4*)&Bs[tid >> 4][(tid & 15) * 4] = rb;
}

// A fragment read: the 4 b64 fragments (ty8+2p)^swz all lie in the 32B block
// at base = ty8 ^ (swz & 24), permuted by perm = (swz>>1)&3. Two LDS.128 +
// compile-time register permutation (kk fully unrolled).
__device__ __forceinline__ void g1_compute(const float As[BK][MT], const float Bs[BK][64],
                                           int k_lo, int k_hi, int ty8, int tx,
                                           unsigned long long acc[4][8]) {
#pragma unroll
    for (int kk = k_lo; kk < k_hi; kk++) {
        const int swz  = (2 * kk) & 31;
        const int base = ty8 ^ (swz & 24);
        const int perm = (swz >> 1) & 3;
        ulonglong2 la = *(const ulonglong2*)&As[kk][base];
        ulonglong2 lb = *(const ulonglong2*)&As[kk][base + 4];
        unsigned long long ch[4] = {la.x, la.y, lb.x, lb.y};
        unsigned long long a[4];
#pragma unroll
        for (int p = 0; p < 4; p++) a[p] = ch[p ^ perm];

        float4 u0 = *(const float4*)&Bs[kk][tx * 8];
        float4 u1 = *(const float4*)&Bs[kk][tx * 8 + 4];
        const float bj[8] = {u0.x, u0.y, u0.z, u0.w, u1.x, u1.y, u1.z, u1.w};
#pragma unroll
        for (int j = 0; j < 8; j++) {
            unsigned long long bb = pack2(bj[j], bj[j]);
#pragma unroll
            for (int p = 0; p < 4; p++) fma2(acc[p][j], a[p], bb);
        }
    }
}

__global__ __launch_bounds__(256, 2) void gemm1_k(const float* __restrict__ X,
                                                  const float* __restrict__ W,
                                                  const float* __restrict__ asw,
                                                  const float* __restrict__ adw) {
    __shared__ float As[2][BK][MT];
    __shared__ float Bs[2][BK][64];
    __shared__ unsigned sMax[8];
    const int tid = threadIdx.x;
    const int m0  = blockIdx.x * MT;
    const int tx  = tid & 7;
    const int ty8 = (tid >> 3) * 8;
    const int lrow0 = tid >> 1;
    const int lh    = (tid & 1) * 8;
    if (tid < 8) sMax[tid] = ENC_NEG_INF;

    unsigned long long acc[4][8];
#pragma unroll
    for (int p = 0; p < 4; p++)
#pragma unroll
        for (int j = 0; j < 8; j++) acc[p][j] = 0ull;

    {
        float4 ra[2][2]; float4 rb;
        g1_load(X, m0, 0, lrow0, lh, W, tid, ra, rb);
        g1_store(As[0], Bs[0], lrow0, lh, tid, ra, rb);
    }
    __syncthreads();

    const int NT = F_IN / BK;
    for (int kt = 0; kt < NT; kt++) {
        const int cur = kt & 1;
        float4 ra[2][2]; float4 rb;
        const bool more = (kt + 1) < NT;
        if (more) g1_load(X, m0, (kt + 1) * BK, lrow0, lh, W, tid, ra, rb);

        g1_compute(As[cur], Bs[cur], 0, 8, ty8, tx, acc);
        if (more) g1_store(As[cur ^ 1], Bs[cur ^ 1], lrow0, lh, tid, ra, rb);
        g1_compute(As[cur], Bs[cur], 8, 16, ty8, tx, acc);
        __syncthreads();
    }

    float sa[8], da[8];
#pragma unroll
    for (int j = 0; j < 8; j++) {
        sa[j] = __ldg(asw + tx * 8 + j);
        da[j] = __ldg(adw + tx * 8 + j);
    }
    float lmax = -1e30f;
#pragma unroll
    for (int p = 0; p < 4; p++) {
        float2 f[8];
#pragma unroll
        for (int j = 0; j < 8; j++) f[j] = unpack2(acc[p][j]);
#pragma unroll
        for (int e = 0; e < 2; e++) {
            int gm = m0 + ty8 + 2 * p + e;
            if (gm < N_NODES) {
                float o[8];
#pragma unroll
                for (int j = 0; j < 8; j++) o[j] = e ? f[j].y : f[j].x;
                union { __half2 h[4]; float4 f4; } u;
#pragma unroll
                for (int q = 0; q < 4; q++)
                    u.h[q] = __floats2half2_rn(o[2 * q], o[2 * q + 1]);
                *(float4*)(g_h1 + (size_t)gm * C1 + tx * 8) = u.f4;
                float sv = 0.f, dv = 0.f;
#pragma unroll
                for (int j = 0; j < 8; j++) { sv += o[j] * sa[j]; dv += o[j] * da[j]; }
                g_as1[(size_t)gm * 8 + tx] = sv;
                g_ad1[(size_t)gm * 8 + tx] = dv;
                lmax = fmaxf(lmax, sv);
            }
        }
    }
    atomicMax(&sMax[tx], fenc(lmax));
    __syncthreads();
    if (tid < 8) atomicMax(&g_gmax1[tid], sMax[tid]);
}

// ---------------- CSR build ----------------
__global__ void initcnt_k() {
    int n = blockIdx.x * blockDim.x + threadIdx.x;
    if (n < N_NODES) g_cnt[n] = 1;
}

__global__ void count_k(const void* ei) {
    long long e = 2 * ((long long)blockIdx.x * blockDim.x + threadIdx.x);
    if (e >= N_EDGES) return;
    int d0, d1;
    if (g_is64) {
        longlong2 v = *(const longlong2*)((const long long*)ei + N_EDGES + e);
        d0 = (int)v.x; d1 = (int)v.y;
    } else {
        int2 v = *(const int2*)((const int*)ei + N_EDGES + e);
        d0 = v.x; d1 = v.y;
    }
    atomicAdd(&g_cnt[d0], 1);
    atomicAdd(&g_cnt[d1], 1);
}

__global__ void scan1_k() {
    __shared__ int ws[32];
    const int b = blockIdx.x, t = threadIdx.x;
    const int i = b * 1024 + t;
    int v = (i < N_NODES) ? g_cnt[i] : 0;
    const int lane = t & 31, w = t >> 5;
    int x = v;
#pragma unroll
    for (int o = 1; o < 32; o <<= 1) {
        int y = __shfl_up_sync(0xffffffffu, x, o);
        if (lane >= o) x += y;
    }
    if (lane == 31) ws[w] = x;
    __syncthreads();
    if (w == 0) {
        int y = ws[lane];
#pragma unroll
        for (int o = 1; o < 32; o <<= 1) {
            int z = __shfl_up_sync(0xffffffffu, y, o);
            if (lane >= o) y += z;
        }
        ws[lane] = y;
    }
    __syncthreads();
    int off  = (w > 0) ? ws[w - 1] : 0;
    int incl = x + off;
    if (i < N_NODES) g_rowptr[i] = incl - v;
    if (t == 1023) g_part[b] = incl;
}

__global__ void scan2_k() {
    __shared__ int buf[128];
    int t = threadIdx.x;
    buf[t] = (t < NB1024) ? g_part[t] : 0;
    __syncthreads();
#pragma unroll
    for (int o = 1; o < 128; o <<= 1) {
        int y = (t >= o) ? buf[t - o] : 0;
        __syncthreads();
        buf[t] += y;
        __syncthreads();
    }
    g_part2[t] = buf[t];
}

__global__ void scan3_selfloop_k() {
    int b = blockIdx.x, i = b * 1024 + threadIdx.x;
    if (i == 0) g_rowptr[N_NODES] = TOTE;
    if (i >= N_NODES) return;
    int off = (b > 0) ? g_part2[b - 1] : 0;
    int p = g_rowptr[i] + off;
    g_rowptr[i] = p;
    g_srcs[p]   = i;
    g_woff[i]   = p + 1;
}

__global__ void scatter_k(const void* ei) {
    long long e = 2 * ((long long)blockIdx.x * blockDim.x + threadIdx.x);
    if (e >= N_EDGES) return;
    int s0, s1, d0, d1;
    if (g_is64) {
        longlong2 sv = *(const longlong2*)((const long long*)ei + e);
        longlong2 dv = *(const longlong2*)((const long long*)ei + N_EDGES + e);
        s0 = (int)sv.x; s1 = (int)sv.y; d0 = (int)dv.x; d1 = (int)dv.y;
    } else {
        int2 sv = *(const int2*)((const int*)ei + e);
        int2 dv = *(const int2*)((const int*)ei + N_EDGES + e);
        s0 = sv.x; s1 = sv.y; d0 = dv.x; d1 = dv.y;
    }
    int p0 = atomicAdd(&g_woff[d0], 1);
    g_srcs[p0] = s0;
    int p1 = atomicAdd(&g_woff[d1], 1);
    g_srcs[p1] = s1;
}

// ---------------- layer1 aggregate: 8ch x 4-edge-way gather (LDG.128) ----------------
#define ALS 36   // sAl edge-stride: bank = (4*h + e) % 32 -> conflict-free

__global__ void agg1_k(const float* __restrict__ b1) {
    const int gw   = (blockIdx.x * blockDim.x + threadIdx.x) >> 5;
    const int lane = threadIdx.x & 31;
    const int w    = threadIdx.x >> 5;
    __shared__ float sAl [8][8][ALS];
    __shared__ int   sSrc[8][32];
    if (gw >= N_NODES) return;
    const int beg = g_rowptr[gw], end = g_rowptr[gw + 1];

    const int hh = (lane & 1) * 4;
    float ad4[4], mh4[4];
    {
        float4 a = *(const float4*)(g_ad1 + (size_t)gw * 8 + hh);
        ad4[0] = a.x; ad4[1] = a.y; ad4[2] = a.z; ad4[3] = a.w;
#pragma unroll
        for (int j = 0; j < 4; j++)
            mh4[j] = leaky02(fdec(g_gmax1[hh + j]) + ad4[j]);
    }

    const int g8 = lane & 7;
    const int ew = lane >> 3;
    float ws4[4] = {0.f, 0.f, 0.f, 0.f};
    float a[8];
#pragma unroll
    for (int k = 0; k < 8; k++) a[k] = 0.f;

    int chunk = beg;
    for (; chunk + 32 <= end; chunk += 32) {
        sSrc[w][lane] = g_srcs[chunk + lane];
        __syncwarp();
#pragma unroll
        for (int sub = 0; sub < 2; sub++) {
            const int e16 = sub * 16 + (lane >> 1);
            const int sxl = sSrc[w][e16];
            float4 u = *(const float4*)(g_as1 + (size_t)sxl * 8 + hh);
            const float uv[4] = {u.x, u.y, u.z, u.w};
#pragma unroll
            for (int j = 0; j < 4; j++) {
                float e = __expf(leaky02(uv[j] + ad4[j]) - mh4[j]);
                ws4[j] += e;
                sAl[w][hh + j][e16] = e;
            }
        }
        __syncwarp();
#pragma unroll
        for (int e0 = 0; e0 < 32; e0 += 4) {
            const int edge = e0 + ew;
            const int   sy = sSrc[w][edge];
            const float al = sAl[w][g8][edge];
            uint4 hv = *(const uint4*)(g_h1 + (size_t)sy * C1 + g8 * 8);
            float2 p0 = __half22float2(*(const __half2*)&hv.x);
            float2 p1 = __half22float2(*(const __half2*)&hv.y);
            float2 p2 = __half22float2(*(const __half2*)&hv.z);
            float2 p3 = __half22float2(*(const __half2*)&hv.w);
            a[0] += p0.x * al; a[1] += p0.y * al;
            a[2] += p1.x * al; a[3] += p1.y * al;
            a[4] += p2.x * al; a[5] += p2.y * al;
            a[6] += p3.x * al; a[7] += p3.y * al;
        }
        __syncwarp();
    }

    const int r = end - chunk;
    if (r > 0) {
        int i = chunk + lane;
        sSrc[w][lane] = (i < end) ? g_srcs[i] : gw;
        __syncwarp();
#pragma unroll
        for (int sub = 0; sub < 2; sub++) {
            const int e16 = sub * 16 + (lane >> 1);
            const bool valid = e16 < r;
            const int sxl = sSrc[w][e16];
            float4 u = *(const float4*)(g_as1 + (size_t)sxl * 8 + hh);
            const float uv[4] = {u.x, u.y, u.z, u.w};
#pragma unroll
            for (int j = 0; j < 4; j++) {
                float e = valid ? __expf(leaky02(uv[j] + ad4[j]) - mh4[j]) : 0.f;
                ws4[j] += e;
                sAl[w][hh + j][e16] = e;
            }
        }
        __syncwarp();
        if (r <= 16) {
#pragma unroll
            for (int e0 = 0; e0 < 16; e0 += 4) {
                const int edge = e0 + ew;
                const int   sy = sSrc[w][edge];
                const float al = sAl[w][g8][edge];
                uint4 hv = *(const uint4*)(g_h1 + (size_t)sy * C1 + g8 * 8);
                float2 p0 = __half22float2(*(const __half2*)&hv.x);
                float2 p1 = __half22float2(*(const __half2*)&hv.y);
                float2 p2 = __half22float2(*(const __half2*)&hv.z);
                float2 p3 = __half22float2(*(const __half2*)&hv.w);
                a[0] += p0.x * al; a[1] += p0.y * al;
                a[2] += p1.x * al; a[3] += p1.y * al;
                a[4] += p2.x * al; a[5] += p2.y * al;
                a[6] += p3.x * al; a[7] += p3.y * al;
            }
        } else {
#pragma unroll
            for (int e0 = 0; e0 < 32; e0 += 4) {
                const int edge = e0 + ew;
                const int   sy = sSrc[w][edge];
                const float al = sAl[w][g8][edge];
                uint4 hv = *(const uint4*)(g_h1 + (size_t)sy * C1 + g8 * 8);
                float2 p0 = __half22float2(*(const __half2*)&hv.x);
                float2 p1 = __half22float2(*(const __half2*)&hv.y);
                float2 p2 = __half22float2(*(const __half2*)&hv.z);
                float2 p3 = __half22float2(*(const __half2*)&hv.w);
                a[0] += p0.x * al; a[1] += p0.y * al;
                a[2] += p1.x * al; a[3] += p1.y * al;
                a[4] += p2.x * al; a[5] += p2.y * al;
                a[6] += p3.x * al; a[7] += p3.y * al;
            }
        }
        __syncwarp();
    }

#pragma unroll
    for (int o = 2; o <= 16; o <<= 1)
#pragma unroll
        for (int j = 0; j < 4; j++)
            ws4[j] += __shfl_xor_sync(0xffffffffu, ws4[j], o);

#pragma unroll
    for (int k = 0; k < 8; k++) {
        a[k] += __shfl_xor_sync(0xffffffffu, a[k], 8);
        a[k] += __shfl_xor_sync(0xffffffffu, a[k], 16);
    }

    float se[4], so[4];
#pragma unroll
    for (int j = 0; j < 4; j++) {
        se[j] = __shfl_sync(0xffffffffu, ws4[j], 0);
        so[j] = __shfl_sync(0xffffffffu, ws4[j], 1);
    }

    if (lane < 8) {
        const int h = lane;
        float wsh = (h < 4) ? se[h] : so[h - 4];
        const float rsh = 1.0f / wsh;
        float4 b0 = *(const float4*)(b1 + h * 8);
        float4 b1v = *(const float4*)(b1 + h * 8 + 4);
        const float bb[8] = {b0.x, b0.y, b0.z, b0.w, b1v.x, b1v.y, b1v.z, b1v.w};
        float o[8];
#pragma unroll
        for (int k = 0; k < 8; k++) {
            float v = a[k] * rsh + bb[k];
            o[k] = (v > 0.f) ? v : (__expf(v) - 1.0f);
        }
        *(float4*)(g_hact + (size_t)gw * C1 + h * 8)     = make_float4(o[0], o[1], o[2], o[3]);
        *(float4*)(g_hact + (size_t)gw * C1 + h * 8 + 4) = make_float4(o[4], o[5], o[6], o[7]);
    }
}

// ---------------- layer2 GEMM + attn coefs + fused max ----------------
__global__ void gemm2_attn_k(const float* __restrict__ W2,
                             const float* __restrict__ asrc2,
                             const float* __restrict__ adst2) {
    __shared__ float Xs[16 * 64];
    __shared__ float Ws[64 * 16];
    __shared__ unsigned sM2;
    const int tid = threadIdx.x;
    const int n0  = blockIdx.x * 16;
    if (tid == 0) sM2 = ENC_NEG_INF;

    ((float4*)Ws)[tid] = ((const float4*)W2)[tid];
    {
        int row = tid >> 4;
        float4 v = make_float4(0.f, 0.f, 0.f, 0.f);
        if (n0 + row < N_NODES)
            v = ((const float4*)(g_hact + (size_t)n0 * C1))[tid];
        ((float4*)Xs)[tid] = v;
    }
    __syncthreads();

    const int r = tid >> 4, c = tid & 15;
    float acc = 0.f;
#pragma unroll
    for (int k = 0; k < 64; k++) acc += Xs[r * 64 + k] * Ws[k * 16 + c];
    const int n = n0 + r;
    if (n < N_NODES) g_h2[(size_t)n * NCLS + c] = __float2half_rn(acc);

    float vs = acc * asrc2[c];
    float vd = acc * adst2[c];
#pragma unroll
    for (int off = 8; off; off >>= 1) {
        vs += __shfl_xor_sync(0xffffffffu, vs, off);
        vd += __shfl_xor_sync(0xffffffffu, vd, off);
    }
    if (c == 0) {
        if (n < N_NODES) {
            g_as2[n] = vs;
            g_ad2[n] = vd;
            atomicMax(&sM2, fenc(vs));
        }
    }
    __syncthreads();
    if (tid == 0) atomicMax(&g_gmax2, sM2);
}

// ---------------- layer2 aggregate: full chunks + sized tail ----------------
__global__ void agg2_k(const float* __restrict__ b2, float* __restrict__ out) {
    const int gw   = (blockIdx.x * blockDim.x + threadIdx.x) >> 5;
    const int lane = threadIdx.x & 31;
    const int w    = threadIdx.x >> 5;
    __shared__ float sAl [8][32];
    __shared__ int   sSrc[8][32];
    if (gw >= N_NODES) return;
    const int beg = g_rowptr[gw], end = g_rowptr[gw + 1];
    const float adn = g_ad2[gw];
    const float mh  = leaky02(fdec(g_gmax2) + adn);

    const int c    = lane & 15;
    const int half = lane >> 4;
    float acc = 0.f, ws = 0.f;

    int chunk = beg;
    for (; chunk + 32 <= end; chunk += 32) {
        const int sx = g_srcs[chunk + lane];
        const float e = __expf(leaky02(g_as2[sx] + adn) - mh);
        ws += e;
        sSrc[w][lane] = sx;
        sAl [w][lane] = e;
        __syncwarp();
#pragma unroll
        for (int e0 = 0; e0 < 32; e0 += 2) {
            const int edge = e0 + half;
            acc += __half2float(g_h2[(size_t)sSrc[w][edge] * NCLS + c]) * sAl[w][edge];
        }
        __syncwarp();
    }

    const int r = end - chunk;
    if (r > 0) {
        int i = chunk + lane;
        int sx = gw;
        float e = 0.f;
        if (i < end) {
            sx = g_srcs[i];
            e  = __expf(leaky02(g_as2[sx] + adn) - mh);
            ws += e;
        }
        sSrc[w][lane] = sx;
        sAl [w][lane] = e;
        __syncwarp();
        if (r <= 16) {
#pragma unroll
            for (int e0 = 0; e0 < 16; e0 += 2) {
                const int edge = e0 + half;
                acc += __half2float(g_h2[(size_t)sSrc[w][edge] * NCLS + c]) * sAl[w][edge];
            }
        } else {
#pragma unroll
            for (int e0 = 0; e0 < 32; e0 += 2) {
                const int edge = e0 + half;
                acc += __half2float(g_h2[(size_t)sSrc[w][edge] * NCLS + c]) * sAl[w][edge];
            }
        }
        __syncwarp();
    }

#pragma unroll
    for (int o = 16; o; o >>= 1)
        ws += __shfl_xor_sync(0xffffffffu, ws, o);
    const float rs = 1.0f / ws;

    acc += __shfl_down_sync(0xffffffffu, acc, 16);
    if (lane < 16) out[(size_t)gw * NCLS + c] = acc * rs + b2[c];
}

// ---------------- streams for graph fork/join ----------------
static cudaStream_t g_s1;
static cudaEvent_t  g_ev0, g_ev1;
namespace {
struct StreamInit {
    StreamInit() {
        cudaStreamCreateWithFlags(&g_s1, cudaStreamNonBlocking);
        cudaEventCreateWithFlags(&g_ev0, cudaEventDisableTiming);
        cudaEventCreateWithFlags(&g_ev1, cudaEventDisableTiming);
    }
};
static StreamInit g_streaminit;
}

// ---------------- launch ----------------
extern "C" void kernel_launch(void* const* d_in, const int* in_sizes, int n_in,
                              void* d_out, int out_size) {
    const float* x    = (const float*)d_in[0];
    const void*  ei   = d_in[1];
    const float* W1   = (const float*)d_in[2];
    const float* as1w = (const float*)d_in[3];
    const float* ad1w = (const float*)d_in[4];
    const float* b1   = (const float*)d_in[5];
    const float* W2   = (const float*)d_in[6];
    const float* as2w = (const float*)d_in[7];
    const float* ad2w = (const float*)d_in[8];
    const float* b2   = (const float*)d_in[9];
    float* out = (float*)d_out;

    probe_k<<<1, 256>>>(ei);                                          // launch 0

    cudaEventRecord(g_ev0, 0);
    cudaStreamWaitEvent(g_s1, g_ev0, 0);

    initcnt_k<<<(N_NODES + 255) / 256, 256, 0, g_s1>>>();             // launch 1
    count_k<<<(N_EDGES / 2 + 255) / 256, 256, 0, g_s1>>>(ei);         // launch 2

    gemm1_k<<<(N_NODES + MT - 1) / MT, 256>>>(x, W1, as1w, ad1w);     // launch 3 (ncu slot)

    scan1_k<<<NB1024, 1024, 0, g_s1>>>();
    scan2_k<<<1, 128, 0, g_s1>>>();
    scan3_selfloop_k<<<NB1024, 1024, 0, g_s1>>>();
    scatter_k<<<(N_EDGES / 2 + 255) / 256, 256, 0, g_s1>>>(ei);
    cudaEventRecord(g_ev1, g_s1);

    cudaStreamWaitEvent(0, g_ev1, 0);

    agg1_k<<<(N_NODES + 7) / 8, 256>>>(b1);
    gemm2_attn_k<<<(N_NODES + 15) / 16, 256>>>(W2, as2w, ad2w);
    agg2_k<<<(N_NODES + 7) / 8, 256>>>(b2, out);
}

// round 16
// speedup vs baseline: 1.0391x; 1.0391x over previous
#include <cuda_runtime.h>
#include <cuda_fp16.h>
#include <cstdint>

// ---------------- problem constants ----------------
#define N_NODES 100000
#define N_EDGES 3200000
#define F_IN    512
#define HEADS   8
#define HID     8
#define C1      64
#define NCLS    16
#define TOTE    (N_EDGES + N_NODES)
#define NB1024  ((N_NODES + 1023) / 1024)

// ---------------- device scratch ----------------
__device__ __half g_h1  [(size_t)N_NODES * C1];
__device__ float  g_hact[(size_t)N_NODES * C1];
__device__ float  g_as1 [(size_t)N_NODES * HEADS];
__device__ float  g_ad1 [(size_t)N_NODES * HEADS];
__device__ __half g_h2  [(size_t)N_NODES * NCLS];
__device__ float  g_as2 [N_NODES];
__device__ float  g_ad2 [N_NODES];
__device__ int    g_rowptr[N_NODES + 1];
__device__ int    g_cnt [N_NODES];
__device__ int    g_woff[N_NODES];
__device__ int    g_srcs[TOTE];
__device__ int    g_part [128];
__device__ int    g_part2[128];
__device__ int    g_is64;
__device__ unsigned g_gmax1[8];
__device__ unsigned g_gmax2;

// ---------------- helpers ----------------
__device__ __forceinline__ float leaky02(float x) { return fmaxf(x, 0.2f * x); }

__device__ __forceinline__ unsigned long long pack2(float x, float y) {
    unsigned long long r;
    asm("mov.b64 %0,{%1,%2};" : "=l"(r) : "f"(x), "f"(y));
    return r;
}
__device__ __forceinline__ void fma2(unsigned long long& d, unsigned long long a, unsigned long long b) {
    asm("fma.rn.f32x2 %0,%1,%2,%0;" : "+l"(d) : "l"(a), "l"(b));
}
__device__ __forceinline__ float2 unpack2(unsigned long long v) {
    float2 f;
    asm("mov.b64 {%0,%1},%2;" : "=f"(f.x), "=f"(f.y) : "l"(v));
    return f;
}
__device__ __forceinline__ unsigned fenc(float f) {
    unsigned u = __float_as_uint(f);
    return (u & 0x80000000u) ? ~u : (u | 0x80000000u);
}
__device__ __forceinline__ float fdec(unsigned u) {
    return __uint_as_float((u & 0x80000000u) ? (u & 0x7FFFFFFFu) : ~u);
}
#define ENC_NEG_INF 0x007FFFFFu

// ---------------- dtype probe + per-call resets ----------------
__global__ void probe_k(const void* ei) {
    __shared__ int s_bad;
    if (threadIdx.x < 8)  g_gmax1[threadIdx.x] = ENC_NEG_INF;
    if (threadIdx.x == 8) g_gmax2 = ENC_NEG_INF;
    if (threadIdx.x == 0) s_bad = 0;
    __syncthreads();
    const long long* p = (const long long*)ei;
    for (int i = threadIdx.x; i < 1024; i += blockDim.x) {
        long long v = p[i];
        if ((v >> 32) != 0) s_bad = 1;
    }
    __syncthreads();
    if (threadIdx.x == 0) g_is64 = (s_bad == 0) ? 1 : 0;
}

// ---------------- GEMM1 + fused attn coefs + fused head-max (R14 proven) ----------------
#define MT 256
#define BK 16

__device__ __forceinline__ void g1_load(const float* __restrict__ X, int m0, int k0,
                                        int lrow0, int lh, const float* __restrict__ W,
                                        int tid, float4 ra[2][2], float4& rb) {
#pragma unroll
    for (int s = 0; s < 2; s++) {
        int row = lrow0 + s * 128;
        int gm  = m0 + row;
        if (gm < N_NODES) {
            const float4* p = (const float4*)(X + (size_t)gm * F_IN + k0 + lh);
            ra[s][0] = p[0];
            ra[s][1] = p[1];
        } else {
            ra[s][0] = make_float4(0.f, 0.f, 0.f, 0.f);
            ra[s][1] = make_float4(0.f, 0.f, 0.f, 0.f);
        }
    }
    rb = *(const float4*)(W + (size_t)(k0 + (tid >> 4)) * 64 + (tid & 15) * 4);
}

__device__ __forceinline__ void g1_store(float As[BK][MT], float Bs[BK][64],
                                         int lrow0, int lh, int tid,
                                         const float4 ra[2][2], const float4& rb) {
#pragma unroll
    for (int s = 0; s < 2; s++) {
        int row = lrow0 + s * 128;
        const float* f = (const float*)&ra[s][0];
#pragma unroll
        for (int j = 0; j < 8; j++) {
            int k = lh + j;
            As[k][row ^ ((2 * k) & 31)] = f[j];
        }
    }
    *(float4*)&Bs[tid >> 4][(tid & 15) * 4] = rb;
}

__device__ __forceinline__ void g1_compute(const float As[BK][MT], const float Bs[BK][64],
                                           int k_lo, int k_hi, int ty8, int tx,
                                           unsigned long long acc[4][8]) {
#pragma unroll
    for (int kk = k_lo; kk < k_hi; kk++) {
        const int swz = (2 * kk) & 31;
        unsigned long long a[4];
#pragma unroll
        for (int p = 0; p < 4; p++)
            a[p] = *(const unsigned long long*)&As[kk][(ty8 + 2 * p) ^ swz];
        float4 u0 = *(const float4*)&Bs[kk][tx * 8];
        float4 u1 = *(const float4*)&Bs[kk][tx * 8 + 4];
        const float bj[8] = {u0.x, u0.y, u0.z, u0.w, u1.x, u1.y, u1.z, u1.w};
#pragma unroll
        for (int j = 0; j < 8; j++) {
            unsigned long long bb = pack2(bj[j], bj[j]);
#pragma unroll
            for (int p = 0; p < 4; p++) fma2(acc[p][j], a[p], bb);
        }
    }
}

__global__ __launch_bounds__(256, 2) void gemm1_k(const float* __restrict__ X,
                                                  const float* __restrict__ W,
                                                  const float* __restrict__ asw,
                                                  const float* __restrict__ adw) {
    __shared__ float As[2][BK][MT];
    __shared__ float Bs[2][BK][64];
    __shared__ unsigned sMax[8];
    const int tid = threadIdx.x;
    const int m0  = blockIdx.x * MT;
    const int tx  = tid & 7;
    const int ty8 = (tid >> 3) * 8;
    const int lrow0 = tid >> 1;
    const int lh    = (tid & 1) * 8;
    if (tid < 8) sMax[tid] = ENC_NEG_INF;

    unsigned long long acc[4][8];
#pragma unroll
    for (int p = 0; p < 4; p++)
#pragma unroll
        for (int j = 0; j < 8; j++) acc[p][j] = 0ull;

    {
        float4 ra[2][2]; float4 rb;
        g1_load(X, m0, 0, lrow0, lh, W, tid, ra, rb);
        g1_store(As[0], Bs[0], lrow0, lh, tid, ra, rb);
    }
    __syncthreads();

    const int NT = F_IN / BK;
    for (int kt = 0; kt < NT; kt++) {
        const int cur = kt & 1;
        float4 ra[2][2]; float4 rb;
        const bool more = (kt + 1) < NT;
        if (more) g1_load(X, m0, (kt + 1) * BK, lrow0, lh, W, tid, ra, rb);

        g1_compute(As[cur], Bs[cur], 0, 8, ty8, tx, acc);
        if (more) g1_store(As[cur ^ 1], Bs[cur ^ 1], lrow0, lh, tid, ra, rb);
        g1_compute(As[cur], Bs[cur], 8, 16, ty8, tx, acc);
        __syncthreads();
    }

    float sa[8], da[8];
#pragma unroll
    for (int j = 0; j < 8; j++) {
        sa[j] = __ldg(asw + tx * 8 + j);
        da[j] = __ldg(adw + tx * 8 + j);
    }
    float lmax = -1e30f;
#pragma unroll
    for (int p = 0; p < 4; p++) {
        float2 f[8];
#pragma unroll
        for (int j = 0; j < 8; j++) f[j] = unpack2(acc[p][j]);
#pragma unroll
        for (int e = 0; e < 2; e++) {
            int gm = m0 + ty8 + 2 * p + e;
            if (gm < N_NODES) {
                float o[8];
#pragma unroll
                for (int j = 0; j < 8; j++) o[j] = e ? f[j].y : f[j].x;
                union { __half2 h[4]; float4 f4; } u;
#pragma unroll
                for (int q = 0; q < 4; q++)
                    u.h[q] = __floats2half2_rn(o[2 * q], o[2 * q + 1]);
                *(float4*)(g_h1 + (size_t)gm * C1 + tx * 8) = u.f4;
                float sv = 0.f, dv = 0.f;
#pragma unroll
                for (int j = 0; j < 8; j++) { sv += o[j] * sa[j]; dv += o[j] * da[j]; }
                g_as1[(size_t)gm * 8 + tx] = sv;
                g_ad1[(size_t)gm * 8 + tx] = dv;
                lmax = fmaxf(lmax, sv);
            }
        }
    }
    atomicMax(&sMax[tx], fenc(lmax));
    __syncthreads();
    if (tid < 8) atomicMax(&g_gmax1[tid], sMax[tid]);
}

// ---------------- CSR build ----------------
__global__ void initcnt_k() {
    int n = blockIdx.x * blockDim.x + threadIdx.x;
    if (n < N_NODES) g_cnt[n] = 1;
}

__global__ void count_k(const void* ei) {
    long long e = 2 * ((long long)blockIdx.x * blockDim.x + threadIdx.x);
    if (e >= N_EDGES) return;
    int d0, d1;
    if (g_is64) {
        longlong2 v = *(const longlong2*)((const long long*)ei + N_EDGES + e);
        d0 = (int)v.x; d1 = (int)v.y;
    } else {
        int2 v = *(const int2*)((const int*)ei + N_EDGES + e);
        d0 = v.x; d1 = v.y;
    }
    atomicAdd(&g_cnt[d0], 1);
    atomicAdd(&g_cnt[d1], 1);
}

__global__ void scan1_k() {
    __shared__ int ws[32];
    const int b = blockIdx.x, t = threadIdx.x;
    const int i = b * 1024 + t;
    int v = (i < N_NODES) ? g_cnt[i] : 0;
    const int lane = t & 31, w = t >> 5;
    int x = v;
#pragma unroll
    for (int o = 1; o < 32; o <<= 1) {
        int y = __shfl_up_sync(0xffffffffu, x, o);
        if (lane >= o) x += y;
    }
    if (lane == 31) ws[w] = x;
    __syncthreads();
    if (w == 0) {
        int y = ws[lane];
#pragma unroll
        for (int o = 1; o < 32; o <<= 1) {
            int z = __shfl_up_sync(0xffffffffu, y, o);
            if (lane >= o) y += z;
        }
        ws[lane] = y;
    }
    __syncthreads();
    int off  = (w > 0) ? ws[w - 1] : 0;
    int incl = x + off;
    if (i < N_NODES) g_rowptr[i] = incl - v;
    if (t == 1023) g_part[b] = incl;
}

__global__ void scan2_k() {
    __shared__ int buf[128];
    int t = threadIdx.x;
    buf[t] = (t < NB1024) ? g_part[t] : 0;
    __syncthreads();
#pragma unroll
    for (int o = 1; o < 128; o <<= 1) {
        int y = (t >= o) ? buf[t - o] : 0;
        __syncthreads();
        buf[t] += y;
        __syncthreads();
    }
    g_part2[t] = buf[t];
}

__global__ void scan3_selfloop_k() {
    int b = blockIdx.x, i = b * 1024 + threadIdx.x;
    if (i == 0) g_rowptr[N_NODES] = TOTE;
    if (i >= N_NODES) return;
    int off = (b > 0) ? g_part2[b - 1] : 0;
    int p = g_rowptr[i] + off;
    g_rowptr[i] = p;
    g_srcs[p]   = i;
    g_woff[i]   = p + 1;
}

__global__ void scatter_k(const void* ei) {
    long long e = 2 * ((long long)blockIdx.x * blockDim.x + threadIdx.x);
    if (e >= N_EDGES) return;
    int s0, s1, d0, d1;
    if (g_is64) {
        longlong2 sv = *(const longlong2*)((const long long*)ei + e);
        longlong2 dv = *(const longlong2*)((const long long*)ei + N_EDGES + e);
        s0 = (int)sv.x; s1 = (int)sv.y; d0 = (int)dv.x; d1 = (int)dv.y;
    } else {
        int2 sv = *(const int2*)((const int*)ei + e);
        int2 dv = *(const int2*)((const int*)ei + N_EDGES + e);
        s0 = sv.x; s1 = sv.y; d0 = dv.x; d1 = dv.y;
    }
    int p0 = atomicAdd(&g_woff[d0], 1);
    g_srcs[p0] = s0;
    int p1 = atomicAdd(&g_woff[d1], 1);
    g_srcs[p1] = s1;
}

// ---------------- layer1 aggregate: 8ch x 4-edge-way gather (R14 proven) ----------------
#define ALS 36

__global__ void agg1_k(const float* __restrict__ b1) {
    const int gw   = (blockIdx.x * blockDim.x + threadIdx.x) >> 5;
    const int lane = threadIdx.x & 31;
    const int w    = threadIdx.x >> 5;
    __shared__ float sAl [8][8][ALS];
    __shared__ int   sSrc[8][32];
    if (gw >= N_NODES) return;
    const int beg = g_rowptr[gw], end = g_rowptr[gw + 1];

    const int hh = (lane & 1) * 4;
    float ad4[4], mh4[4];
    {
        float4 a = *(const float4*)(g_ad1 + (size_t)gw * 8 + hh);
        ad4[0] = a.x; ad4[1] = a.y; ad4[2] = a.z; ad4[3] = a.w;
#pragma unroll
        for (int j = 0; j < 4; j++)
            mh4[j] = leaky02(fdec(g_gmax1[hh + j]) + ad4[j]);
    }

    const int g8 = lane & 7;
    const int ew = lane >> 3;
    float ws4[4] = {0.f, 0.f, 0.f, 0.f};
    float a[8];
#pragma unroll
    for (int k = 0; k < 8; k++) a[k] = 0.f;

    int chunk = beg;
    for (; chunk + 32 <= end; chunk += 32) {
        sSrc[w][lane] = g_srcs[chunk + lane];
        __syncwarp();
#pragma unroll
        for (int sub = 0; sub < 2; sub++) {
            const int e16 = sub * 16 + (lane >> 1);
            const int sxl = sSrc[w][e16];
            float4 u = *(const float4*)(g_as1 + (size_t)sxl * 8 + hh);
            const float uv[4] = {u.x, u.y, u.z, u.w};
#pragma unroll
            for (int j = 0; j < 4; j++) {
                float e = __expf(leaky02(uv[j] + ad4[j]) - mh4[j]);
                ws4[j] += e;
                sAl[w][hh + j][e16] = e;
            }
        }
        __syncwarp();
#pragma unroll
        for (int e0 = 0; e0 < 32; e0 += 4) {
            const int edge = e0 + ew;
            const int   sy = sSrc[w][edge];
            const float al = sAl[w][g8][edge];
            uint4 hv = *(const uint4*)(g_h1 + (size_t)sy * C1 + g8 * 8);
            float2 p0 = __half22float2(*(const __half2*)&hv.x);
            float2 p1 = __half22float2(*(const __half2*)&hv.y);
            float2 p2 = __half22float2(*(const __half2*)&hv.z);
            float2 p3 = __half22float2(*(const __half2*)&hv.w);
            a[0] += p0.x * al; a[1] += p0.y * al;
            a[2] += p1.x * al; a[3] += p1.y * al;
            a[4] += p2.x * al; a[5] += p2.y * al;
            a[6] += p3.x * al; a[7] += p3.y * al;
        }
        __syncwarp();
    }

    const int r = end - chunk;
    if (r > 0) {
        int i = chunk + lane;
        sSrc[w][lane] = (i < end) ? g_srcs[i] : gw;
        __syncwarp();
#pragma unroll
        for (int sub = 0; sub < 2; sub++) {
            const int e16 = sub * 16 + (lane >> 1);
            const bool valid = e16 < r;
            const int sxl = sSrc[w][e16];
            float4 u = *(const float4*)(g_as1 + (size_t)sxl * 8 + hh);
            const float uv[4] = {u.x, u.y, u.z, u.w};
#pragma unroll
            for (int j = 0; j < 4; j++) {
                float e = valid ? __expf(leaky02(uv[j] + ad4[j]) - mh4[j]) : 0.f;
                ws4[j] += e;
                sAl[w][hh + j][e16] = e;
            }
        }
        __syncwarp();
        if (r <= 16) {
#pragma unroll
            for (int e0 = 0; e0 < 16; e0 += 4) {
                const int edge = e0 + ew;
                const int   sy = sSrc[w][edge];
                const float al = sAl[w][g8][edge];
                uint4 hv = *(const uint4*)(g_h1 + (size_t)sy * C1 + g8 * 8);
                float2 p0 = __half22float2(*(const __half2*)&hv.x);
                float2 p1 = __half22float2(*(const __half2*)&hv.y);
                float2 p2 = __half22float2(*(const __half2*)&hv.z);
                float2 p3 = __half22float2(*(const __half2*)&hv.w);
                a[0] += p0.x * al; a[1] += p0.y * al;
                a[2] += p1.x * al; a[3] += p1.y * al;
                a[4] += p2.x * al; a[5] += p2.y * al;
                a[6] += p3.x * al; a[7] += p3.y * al;
            }
        } else {
#pragma unroll
            for (int e0 = 0; e0 < 32; e0 += 4) {
                const int edge = e0 + ew;
                const int   sy = sSrc[w][edge];
                const float al = sAl[w][g8][edge];
                uint4 hv = *(const uint4*)(g_h1 + (size_t)sy * C1 + g8 * 8);
                float2 p0 = __half22float2(*(const __half2*)&hv.x);
                float2 p1 = __half22float2(*(const __half2*)&hv.y);
                float2 p2 = __half22float2(*(const __half2*)&hv.z);
                float2 p3 = __half22float2(*(const __half2*)&hv.w);
                a[0] += p0.x * al; a[1] += p0.y * al;
                a[2] += p1.x * al; a[3] += p1.y * al;
                a[4] += p2.x * al; a[5] += p2.y * al;
                a[6] += p3.x * al; a[7] += p3.y * al;
            }
        }
        __syncwarp();
    }

#pragma unroll
    for (int o = 2; o <= 16; o <<= 1)
#pragma unroll
        for (int j = 0; j < 4; j++)
            ws4[j] += __shfl_xor_sync(0xffffffffu, ws4[j], o);

#pragma unroll
    for (int k = 0; k < 8; k++) {
        a[k] += __shfl_xor_sync(0xffffffffu, a[k], 8);
        a[k] += __shfl_xor_sync(0xffffffffu, a[k], 16);
    }

    float se[4], so[4];
#pragma unroll
    for (int j = 0; j < 4; j++) {
        se[j] = __shfl_sync(0xffffffffu, ws4[j], 0);
        so[j] = __shfl_sync(0xffffffffu, ws4[j], 1);
    }

    if (lane < 8) {
        const int h = lane;
        float wsh = (h < 4) ? se[h] : so[h - 4];
        const float rsh = 1.0f / wsh;
        float4 b0 = *(const float4*)(b1 + h * 8);
        float4 b1v = *(const float4*)(b1 + h * 8 + 4);
        const float bb[8] = {b0.x, b0.y, b0.z, b0.w, b1v.x, b1v.y, b1v.z, b1v.w};
        float o[8];
#pragma unroll
        for (int k = 0; k < 8; k++) {
            float v = a[k] * rsh + bb[k];
            o[k] = (v > 0.f) ? v : (__expf(v) - 1.0f);
        }
        *(float4*)(g_hact + (size_t)gw * C1 + h * 8)     = make_float4(o[0], o[1], o[2], o[3]);
        *(float4*)(g_hact + (size_t)gw * C1 + h * 8 + 4) = make_float4(o[4], o[5], o[6], o[7]);
    }
}

// ---------------- layer2 GEMM + attn coefs + fused max ----------------
__global__ void gemm2_attn_k(const float* __restrict__ W2,
                             const float* __restrict__ asrc2,
                             const float* __restrict__ adst2) {
    __shared__ float Xs[16 * 64];
    __shared__ float Ws[64 * 16];
    __shared__ unsigned sM2;
    const int tid = threadIdx.x;
    const int n0  = blockIdx.x * 16;
    if (tid == 0) sM2 = ENC_NEG_INF;

    ((float4*)Ws)[tid] = ((const float4*)W2)[tid];
    {
        int row = tid >> 4;
        float4 v = make_float4(0.f, 0.f, 0.f, 0.f);
        if (n0 + row < N_NODES)
            v = ((const float4*)(g_hact + (size_t)n0 * C1))[tid];
        ((float4*)Xs)[tid] = v;
    }
    __syncthreads();

    const int r = tid >> 4, c = tid & 15;
    float acc = 0.f;
#pragma unroll
    for (int k = 0; k < 64; k++) acc += Xs[r * 64 + k] * Ws[k * 16 + c];
    const int n = n0 + r;
    if (n < N_NODES) g_h2[(size_t)n * NCLS + c] = __float2half_rn(acc);

    float vs = acc * asrc2[c];
    float vd = acc * adst2[c];
#pragma unroll
    for (int off = 8; off; off >>= 1) {
        vs += __shfl_xor_sync(0xffffffffu, vs, off);
        vd += __shfl_xor_sync(0xffffffffu, vd, off);
    }
    if (c == 0) {
        if (n < N_NODES) {
            g_as2[n] = vs;
            g_ad2[n] = vd;
            atomicMax(&sM2, fenc(vs));
        }
    }
    __syncthreads();
    if (tid == 0) atomicMax(&g_gmax2, sM2);
}

// ---------------- layer2 aggregate: 4ch x 8-edge-way gather (uint2) ----------------
__global__ void agg2_k(const float* __restrict__ b2, float* __restrict__ out) {
    const int gw   = (blockIdx.x * blockDim.x + threadIdx.x) >> 5;
    const int lane = threadIdx.x & 31;
    const int w    = threadIdx.x >> 5;
    __shared__ float sAl [8][32];
    __shared__ int   sSrc[8][32];
    if (gw >= N_NODES) return;
    const int beg = g_rowptr[gw], end = g_rowptr[gw + 1];
    const float adn = g_ad2[gw];
    const float mh  = leaky02(fdec(g_gmax2) + adn);

    const int c4 = (lane & 3) * 4;   // 4 halves per lane
    const int ew = lane >> 2;        // 8 edge ways
    float acc[4] = {0.f, 0.f, 0.f, 0.f};
    float ws = 0.f;

    int chunk = beg;
    for (; chunk + 32 <= end; chunk += 32) {
        const int sx = g_srcs[chunk + lane];
        const float e = __expf(leaky02(g_as2[sx] + adn) - mh);
        ws += e;
        sSrc[w][lane] = sx;
        sAl [w][lane] = e;
        __syncwarp();
#pragma unroll
        for (int e0 = 0; e0 < 32; e0 += 8) {
            const int edge = e0 + ew;
            const int   sy = sSrc[w][edge];
            const float al = sAl[w][edge];
            uint2 hv = *(const uint2*)(g_h2 + (size_t)sy * NCLS + c4);
            float2 p0 = __half22float2(*(const __half2*)&hv.x);
            float2 p1 = __half22float2(*(const __half2*)&hv.y);
            acc[0] += p0.x * al; acc[1] += p0.y * al;
            acc[2] += p1.x * al; acc[3] += p1.y * al;
        }
        __syncwarp();
    }

    const int r = end - chunk;
    if (r > 0) {
        int i = chunk + lane;
        int sx = gw;
        float e = 0.f;
        if (i < end) {
            sx = g_srcs[i];
            e  = __expf(leaky02(g_as2[sx] + adn) - mh);
            ws += e;
        }
        sSrc[w][lane] = sx;
        sAl [w][lane] = e;
        __syncwarp();
        if (r <= 8) {
            const int edge = ew;
            const int   sy = sSrc[w][edge];
            const float al = sAl[w][edge];
            uint2 hv = *(const uint2*)(g_h2 + (size_t)sy * NCLS + c4);
            float2 p0 = __half22float2(*(const __half2*)&hv.x);
            float2 p1 = __half22float2(*(const __half2*)&hv.y);
            acc[0] += p0.x * al; acc[1] += p0.y * al;
            acc[2] += p1.x * al; acc[3] += p1.y * al;
        } else if (r <= 16) {
#pragma unroll
            for (int e0 = 0; e0 < 16; e0 += 8) {
                const int edge = e0 + ew;
                const int   sy = sSrc[w][edge];
                const float al = sAl[w][edge];
                uint2 hv = *(const uint2*)(g_h2 + (size_t)sy * NCLS + c4);
                float2 p0 = __half22float2(*(const __half2*)&hv.x);
                float2 p1 = __half22float2(*(const __half2*)&hv.y);
                acc[0] += p0.x * al; acc[1] += p0.y * al;
                acc[2] += p1.x * al; acc[3] += p1.y * al;
            }
        } else {
#pragma unroll
            for (int e0 = 0; e0 < 32; e0 += 8) {
                const int edge = e0 + ew;
                const int   sy = sSrc[w][edge];
                const float al = sAl[w][edge];
                uint2 hv = *(const uint2*)(g_h2 + (size_t)sy * NCLS + c4);
                float2 p0 = __half22float2(*(const __half2*)&hv.x);
                float2 p1 = __half22float2(*(const __half2*)&hv.y);
                acc[0] += p0.x * al; acc[1] += p0.y * al;
                acc[2] += p1.x * al; acc[3] += p1.y * al;
            }
        }
        __syncwarp();
    }

    // ws total across warp
#pragma unroll
    for (int o = 16; o; o >>= 1)
        ws += __shfl_xor_sync(0xffffffffu, ws, o);
    const float rs = 1.0f / ws;

    // reduce acc over edge-ways (lanes xor 4, 8, 16 share c4)
#pragma unroll
    for (int k = 0; k < 4; k++) {
        acc[k] += __shfl_xor_sync(0xffffffffu, acc[k], 4);
        acc[k] += __shfl_xor_sync(0xffffffffu, acc[k], 8);
        acc[k] += __shfl_xor_sync(0xffffffffu, acc[k], 16);
    }

    if (lane < 4) {
        float4 bb = *(const float4*)(b2 + c4);
        *(float4*)(out + (size_t)gw * NCLS + c4) =
            make_float4(acc[0] * rs + bb.x, acc[1] * rs + bb.y,
                        acc[2] * rs + bb.z, acc[3] * rs + bb.w);
    }
}

// ---------------- streams for graph fork/join ----------------
static cudaStream_t g_s1;
static cudaEvent_t  g_ev0, g_ev1;
namespace {
struct StreamInit {
    StreamInit() {
        cudaStreamCreateWithFlags(&g_s1, cudaStreamNonBlocking);
        cudaEventCreateWithFlags(&g_ev0, cudaEventDisableTiming);
        cudaEventCreateWithFlags(&g_ev1, cudaEventDisableTiming);
    }
};
static StreamInit g_streaminit;
}

// ---------------- launch ----------------
extern "C" void kernel_launch(void* const* d_in, const int* in_sizes, int n_in,
                              void* d_out, int out_size) {
    const float* x    = (const float*)d_in[0];
    const void*  ei   = d_in[1];
    const float* W1   = (const float*)d_in[2];
    const float* as1w = (const float*)d_in[3];
    const float* ad1w = (const float*)d_in[4];
    const float* b1   = (const float*)d_in[5];
    const float* W2   = (const float*)d_in[6];
    const float* as2w = (const float*)d_in[7];
    const float* ad2w = (const float*)d_in[8];
    const float* b2   = (const float*)d_in[9];
    float* out = (float*)d_out;

    probe_k<<<1, 256>>>(ei);

    cudaEventRecord(g_ev0, 0);
    cudaStreamWaitEvent(g_s1, g_ev0, 0);

    initcnt_k<<<(N_NODES + 255) / 256, 256, 0, g_s1>>>();
    count_k<<<(N_EDGES / 2 + 255) / 256, 256, 0, g_s1>>>(ei);

    gemm1_k<<<(N_NODES + MT - 1) / MT, 256>>>(x, W1, as1w, ad1w);

    scan1_k<<<NB1024, 1024, 0, g_s1>>>();
    scan2_k<<<1, 128, 0, g_s1>>>();
    scan3_selfloop_k<<<NB1024, 1024, 0, g_s1>>>();
    scatter_k<<<(N_EDGES / 2 + 255) / 256, 256, 0, g_s1>>>(ei);
    cudaEventRecord(g_ev1, g_s1);

    cudaStreamWaitEvent(0, g_ev1, 0);

    agg1_k<<<(N_NODES + 7) / 8, 256>>>(b1);
    gemm2_attn_k<<<(N_NODES + 15) / 16, 256>>>(W2, as2w, ad2w);
    agg2_k<<<(N_NODES + 7) / 8, 256>>>(b2, out);
}

// round 17
// speedup vs baseline: 1.2404x; 1.1937x over previous
#include <cuda_runtime.h>
#include <cuda_fp16.h>
#include <cuda_bf16.h>
#include <cstdint>

// ---------------- problem constants ----------------
#define N_NODES 100000
#define N_EDGES 3200000
#define F_IN    512
#define HEADS   8
#define HID     8
#define C1      64
#define NCLS    16
#define TOTE    (N_EDGES + N_NODES)
#define NB1024  ((N_NODES + 1023) / 1024)

// HMMA gemm1 tiling
#define GM_M 128
#define GK   32
#define NCH  (F_IN / GK)     // 16
#define AST  40              // bf16 row stride (32 k + 8 pad)
#define ABUF (128 * AST)     // 5120 el
#define BBUF (64 * AST)      // 2560 el
#define OFF_AH 0
#define OFF_AL (2 * ABUF)
#define OFF_BH (4 * ABUF)
#define OFF_BL (4 * ABUF + 2 * BBUF)
#define SM_EL  (4 * ABUF + 4 * BBUF)   // 30720 el = 61440 B

// ---------------- device scratch ----------------
__device__ __half g_h1  [(size_t)N_NODES * C1];
__device__ float  g_hact[(size_t)N_NODES * C1];
__device__ float  g_as1 [(size_t)N_NODES * HEADS];
__device__ float  g_ad1 [(size_t)N_NODES * HEADS];
__device__ __half g_h2  [(size_t)N_NODES * NCLS];
__device__ float  g_as2 [N_NODES];
__device__ float  g_ad2 [N_NODES];
__device__ int    g_rowptr[N_NODES + 1];
__device__ int    g_cnt [N_NODES];
__device__ int    g_woff[N_NODES];
__device__ int    g_srcs[TOTE];
__device__ int    g_part [128];
__device__ int    g_part2[128];
__device__ int    g_is64;
__device__ unsigned g_gmax1[8];
__device__ unsigned g_gmax2;
__device__ __align__(16) __nv_bfloat16 g_Wh[NCH][BBUF];   // [chunk][n][k] hi
__device__ __align__(16) __nv_bfloat16 g_Wl[NCH][BBUF];   // lo

// ---------------- helpers ----------------
__device__ __forceinline__ float leaky02(float x) { return fmaxf(x, 0.2f * x); }

__device__ __forceinline__ unsigned fenc(float f) {
    unsigned u = __float_as_uint(f);
    return (u & 0x80000000u) ? ~u : (u | 0x80000000u);
}
__device__ __forceinline__ float fdec(unsigned u) {
    return __uint_as_float((u & 0x80000000u) ? (u & 0x7FFFFFFFu) : ~u);
}
#define ENC_NEG_INF 0x007FFFFFu

__device__ __forceinline__ void mma16816(float* c,
                                         uint32_t a0, uint32_t a1, uint32_t a2, uint32_t a3,
                                         uint32_t b0, uint32_t b1) {
    asm volatile(
        "mma.sync.aligned.m16n8k16.row.col.f32.bf16.bf16.f32 "
        "{%0,%1,%2,%3}, {%4,%5,%6,%7}, {%8,%9}, {%0,%1,%2,%3};"
        : "+f"(c[0]), "+f"(c[1]), "+f"(c[2]), "+f"(c[3])
        : "r"(a0), "r"(a1), "r"(a2), "r"(a3), "r"(b0), "r"(b1));
}

// ---------------- dtype probe + per-call resets ----------------
__global__ void probe_k(const void* ei) {
    __shared__ int s_bad;
    if (threadIdx.x < 8)  g_gmax1[threadIdx.x] = ENC_NEG_INF;
    if (threadIdx.x == 8) g_gmax2 = ENC_NEG_INF;
    if (threadIdx.x == 0) s_bad = 0;
    __syncthreads();
    const long long* p = (const long long*)ei;
    for (int i = threadIdx.x; i < 1024; i += blockDim.x) {
        long long v = p[i];
        if ((v >> 32) != 0) s_bad = 1;
    }
    __syncthreads();
    if (threadIdx.x == 0) g_is64 = (s_bad == 0) ? 1 : 0;
}

// ---------------- W1 split + transpose (once) ----------------
__global__ void wsplit_k(const float* __restrict__ W) {
    int t = blockIdx.x * blockDim.x + threadIdx.x;
    if (t >= F_IN * C1) return;
    int k = t >> 6, n = t & 63;
    int c = k >> 5, kl = k & 31;
    float x = W[t];   // W[k][n]
    __nv_bfloat16 h = __float2bfloat16(x);
    __nv_bfloat16 l = __float2bfloat16(x - __bfloat162float(h));
    g_Wh[c][n * AST + kl] = h;
    g_Wl[c][n * AST + kl] = l;
}

// ---------------- GEMM1 via pipelined HMMA (split-bf16) ----------------
__device__ __forceinline__ void g1_ldA(const float* __restrict__ X, int m0, int c,
                                       int row, int khalf, float4 ra[4]) {
    const int gm = m0 + row;
    if (gm < N_NODES) {
        const float4* p = (const float4*)(X + (size_t)gm * F_IN + c * GK + khalf);
#pragma unroll
        for (int q = 0; q < 4; q++) ra[q] = p[q];
    } else {
#pragma unroll
        for (int q = 0; q < 4; q++) ra[q] = make_float4(0.f, 0.f, 0.f, 0.f);
    }
}

__device__ __forceinline__ void g1_stA(__nv_bfloat16* Ah, __nv_bfloat16* Al,
                                       int row, int khalf, const float4 ra[4]) {
    const int base = row * AST + khalf;
#pragma unroll
    for (int q = 0; q < 4; q++) {
        float4 v = ra[q];
        __nv_bfloat162 h0 = {__float2bfloat16(v.x), __float2bfloat16(v.y)};
        __nv_bfloat162 h1 = {__float2bfloat16(v.z), __float2bfloat16(v.w)};
        __nv_bfloat162 l0 = {__float2bfloat16(v.x - __bfloat162float(h0.x)),
                             __float2bfloat16(v.y - __bfloat162float(h0.y))};
        __nv_bfloat162 l1 = {__float2bfloat16(v.z - __bfloat162float(h1.x)),
                             __float2bfloat16(v.w - __bfloat162float(h1.y))};
        union { __nv_bfloat162 b[2]; uint2 u; } uh = {{h0, h1}}, ul = {{l0, l1}};
        *(uint2*)&Ah[base + q * 4] = uh.u;
        *(uint2*)&Al[base + q * 4] = ul.u;
    }
}

__device__ __forceinline__ void g1_cpB(__nv_bfloat16* Bh, __nv_bfloat16* Bl, int c, int tid) {
    const uint4* sh = (const uint4*)g_Wh[c];
    const uint4* sl = (const uint4*)g_Wl[c];
    uint4* dh = (uint4*)Bh;
    uint4* dl = (uint4*)Bl;
#pragma unroll
    for (int i = tid; i < 640; i += 256) {
        if (i < 320) dh[i] = sh[i];
        else         dl[i - 320] = sl[i - 320];
    }
}

__device__ __forceinline__ void g1_hmma(const __nv_bfloat16* Ah, const __nv_bfloat16* Al,
                                        const __nv_bfloat16* Bh, const __nv_bfloat16* Bl,
                                        int arow, int g, int tig, int k16, float acc[8][4]) {
    const int ka = k16 * 16 + tig * 2;
    uint32_t ah0 = *(const uint32_t*)&Ah[arow * AST + ka];
    uint32_t ah1 = *(const uint32_t*)&Ah[(arow + 8) * AST + ka];
    uint32_t ah2 = *(const uint32_t*)&Ah[arow * AST + ka + 8];
    uint32_t ah3 = *(const uint32_t*)&Ah[(arow + 8) * AST + ka + 8];
    uint32_t al0 = *(const uint32_t*)&Al[arow * AST + ka];
    uint32_t al1 = *(const uint32_t*)&Al[(arow + 8) * AST + ka];
    uint32_t al2 = *(const uint32_t*)&Al[arow * AST + ka + 8];
    uint32_t al3 = *(const uint32_t*)&Al[(arow + 8) * AST + ka + 8];
#pragma unroll
    for (int nt = 0; nt < 8; nt++) {
        const int n = nt * 8 + g;
        uint32_t bh0 = *(const uint32_t*)&Bh[n * AST + ka];
        uint32_t bh1 = *(const uint32_t*)&Bh[n * AST + ka + 8];
        uint32_t bl0 = *(const uint32_t*)&Bl[n * AST + ka];
        uint32_t bl1 = *(const uint32_t*)&Bl[n * AST + ka + 8];
        mma16816(acc[nt], ah0, ah1, ah2, ah3, bh0, bh1);
        mma16816(acc[nt], ah0, ah1, ah2, ah3, bl0, bl1);
        mma16816(acc[nt], al0, al1, al2, al3, bh0, bh1);
    }
}

__global__ __launch_bounds__(256, 2) void gemm1_k(const float* __restrict__ X,
                                                  const float* __restrict__ asw,
                                                  const float* __restrict__ adw) {
    extern __shared__ __nv_bfloat16 sm[];
    __shared__ unsigned sMax0;
    const int tid  = threadIdx.x;
    const int wid  = tid >> 5;
    const int lane = tid & 31;
    const int g    = lane >> 2;
    const int tig  = lane & 3;
    const int m0   = blockIdx.x * GM_M;
    const int row   = tid >> 1;
    const int khalf = (tid & 1) * 16;
    const int arow  = 16 * wid + g;
    if (tid == 0) sMax0 = ENC_NEG_INF;

    float acc[8][4];
#pragma unroll
    for (int nt = 0; nt < 8; nt++)
#pragma unroll
        for (int j = 0; j < 4; j++) acc[nt][j] = 0.f;

    // prologue: stage chunk 0
    {
        float4 ra[4];
        g1_ldA(X, m0, 0, row, khalf, ra);
        g1_stA(sm + OFF_AH, sm + OFF_AL, row, khalf, ra);
        g1_cpB(sm + OFF_BH, sm + OFF_BL, 0, tid);
    }
    __syncthreads();

    for (int c = 0; c < NCH; c++) {
        const int cur = c & 1;
        const bool more = (c + 1) < NCH;
        const __nv_bfloat16* Ah = sm + OFF_AH + cur * ABUF;
        const __nv_bfloat16* Al = sm + OFF_AL + cur * ABUF;
        const __nv_bfloat16* Bh = sm + OFF_BH + cur * BBUF;
        const __nv_bfloat16* Bl = sm + OFF_BL + cur * BBUF;

        float4 ra[4];
        if (more) g1_ldA(X, m0, c + 1, row, khalf, ra);

        g1_hmma(Ah, Al, Bh, Bl, arow, g, tig, 0, acc);

        if (more) {
            g1_stA(sm + OFF_AH + (cur ^ 1) * ABUF, sm + OFF_AL + (cur ^ 1) * ABUF,
                   row, khalf, ra);
            g1_cpB(sm + OFF_BH + (cur ^ 1) * BBUF, sm + OFF_BL + (cur ^ 1) * BBUF,
                   c + 1, tid);
        }

        g1_hmma(Ah, Al, Bh, Bl, arow, g, tig, 1, acc);
        __syncthreads();
    }

    // epilogue: h1 fp16 + fused as/ad + global max
    float lmax = -1e30f;
#pragma unroll
    for (int e = 0; e < 2; e++) {
        const int gm = m0 + 16 * wid + g + 8 * e;
        const bool ok = gm < N_NODES;
#pragma unroll
        for (int nt = 0; nt < 8; nt++) {
            const float cA = acc[nt][2 * e];
            const float cB = acc[nt][2 * e + 1];
            const int col = nt * 8 + 2 * tig;
            if (ok)
                *(__half2*)(g_h1 + (size_t)gm * C1 + col) = __floats2half2_rn(cA, cB);
            float2 aw = *(const float2*)(asw + col);
            float2 dw = *(const float2*)(adw + col);
            float sv = cA * aw.x + cB * aw.y;
            float dv = cA * dw.x + cB * dw.y;
            sv += __shfl_xor_sync(0xffffffffu, sv, 1);
            sv += __shfl_xor_sync(0xffffffffu, sv, 2);
            dv += __shfl_xor_sync(0xffffffffu, dv, 1);
            dv += __shfl_xor_sync(0xffffffffu, dv, 2);
            if (ok && tig == 0) {
                g_as1[(size_t)gm * 8 + nt] = sv;
                g_ad1[(size_t)gm * 8 + nt] = dv;
                lmax = fmaxf(lmax, sv);
            }
        }
    }
#pragma unroll
    for (int o = 16; o; o >>= 1)
        lmax = fmaxf(lmax, __shfl_xor_sync(0xffffffffu, lmax, o));
    if (lane == 0) atomicMax(&sMax0, fenc(lmax));
    __syncthreads();
    if (tid == 0) atomicMax(&g_gmax1[0], sMax0);
}

// ---------------- CSR build ----------------
__global__ void initcnt_k() {
    int n = blockIdx.x * blockDim.x + threadIdx.x;
    if (n < N_NODES) g_cnt[n] = 1;
}

__global__ void count_k(const void* ei) {
    long long e = 2 * ((long long)blockIdx.x * blockDim.x + threadIdx.x);
    if (e >= N_EDGES) return;
    int d0, d1;
    if (g_is64) {
        longlong2 v = *(const longlong2*)((const long long*)ei + N_EDGES + e);
        d0 = (int)v.x; d1 = (int)v.y;
    } else {
        int2 v = *(const int2*)((const int*)ei + N_EDGES + e);
        d0 = v.x; d1 = v.y;
    }
    atomicAdd(&g_cnt[d0], 1);
    atomicAdd(&g_cnt[d1], 1);
}

__global__ void scan1_k() {
    __shared__ int ws[32];
    const int b = blockIdx.x, t = threadIdx.x;
    const int i = b * 1024 + t;
    int v = (i < N_NODES) ? g_cnt[i] : 0;
    const int lane = t & 31, w = t >> 5;
    int x = v;
#pragma unroll
    for (int o = 1; o < 32; o <<= 1) {
        int y = __shfl_up_sync(0xffffffffu, x, o);
        if (lane >= o) x += y;
    }
    if (lane == 31) ws[w] = x;
    __syncthreads();
    if (w == 0) {
        int y = ws[lane];
#pragma unroll
        for (int o = 1; o < 32; o <<= 1) {
            int z = __shfl_up_sync(0xffffffffu, y, o);
            if (lane >= o) y += z;
        }
        ws[lane] = y;
    }
    __syncthreads();
    int off  = (w > 0) ? ws[w - 1] : 0;
    int incl = x + off;
    if (i < N_NODES) g_rowptr[i] = incl - v;
    if (t == 1023) g_part[b] = incl;
}

__global__ void scan2_k() {
    __shared__ int buf[128];
    int t = threadIdx.x;
    buf[t] = (t < NB1024) ? g_part[t] : 0;
    __syncthreads();
#pragma unroll
    for (int o = 1; o < 128; o <<= 1) {
        int y = (t >= o) ? buf[t - o] : 0;
        __syncthreads();
        buf[t] += y;
        __syncthreads();
    }
    g_part2[t] = buf[t];
}

__global__ void scan3_selfloop_k() {
    int b = blockIdx.x, i = b * 1024 + threadIdx.x;
    if (i == 0) g_rowptr[N_NODES] = TOTE;
    if (i >= N_NODES) return;
    int off = (b > 0) ? g_part2[b - 1] : 0;
    int p = g_rowptr[i] + off;
    g_rowptr[i] = p;
    g_srcs[p]   = i;
    g_woff[i]   = p + 1;
}

__global__ void scatter_k(const void* ei) {
    long long e = 2 * ((long long)blockIdx.x * blockDim.x + threadIdx.x);
    if (e >= N_EDGES) return;
    int s0, s1, d0, d1;
    if (g_is64) {
        longlong2 sv = *(const longlong2*)((const long long*)ei + e);
        longlong2 dv = *(const longlong2*)((const long long*)ei + N_EDGES + e);
        s0 = (int)sv.x; s1 = (int)sv.y; d0 = (int)dv.x; d1 = (int)dv.y;
    } else {
        int2 sv = *(const int2*)((const int*)ei + e);
        int2 dv = *(const int2*)((const int*)ei + N_EDGES + e);
        s0 = sv.x; s1 = sv.y; d0 = dv.x; d1 = dv.y;
    }
    int p0 = atomicAdd(&g_woff[d0], 1);
    g_srcs[p0] = s0;
    int p1 = atomicAdd(&g_woff[d1], 1);
    g_srcs[p1] = s1;
}

// ---------------- layer1 aggregate: 8ch x 4-edge-way gather ----------------
#define ALS 36

__global__ void agg1_k(const float* __restrict__ b1) {
    const int gw   = (blockIdx.x * blockDim.x + threadIdx.x) >> 5;
    const int lane = threadIdx.x & 31;
    const int w    = threadIdx.x >> 5;
    __shared__ float sAl [8][8][ALS];
    __shared__ int   sSrc[8][32];
    if (gw >= N_NODES) return;
    const int beg = g_rowptr[gw], end = g_rowptr[gw + 1];

    const int hh = (lane & 1) * 4;
    float ad4[4], mh4[4];
    {
        float4 a = *(const float4*)(g_ad1 + (size_t)gw * 8 + hh);
        ad4[0] = a.x; ad4[1] = a.y; ad4[2] = a.z; ad4[3] = a.w;
        const float gm = fdec(g_gmax1[0]);   // global upper bound (all heads)
#pragma unroll
        for (int j = 0; j < 4; j++)
            mh4[j] = leaky02(gm + ad4[j]);
    }

    const int g8 = lane & 7;
    const int ew = lane >> 3;
    float ws4[4] = {0.f, 0.f, 0.f, 0.f};
    float a[8];
#pragma unroll
    for (int k = 0; k < 8; k++) a[k] = 0.f;

    int chunk = beg;
    for (; chunk + 32 <= end; chunk += 32) {
        sSrc[w][lane] = g_srcs[chunk + lane];
        __syncwarp();
#pragma unroll
        for (int sub = 0; sub < 2; sub++) {
            const int e16 = sub * 16 + (lane >> 1);
            const int sxl = sSrc[w][e16];
            float4 u = *(const float4*)(g_as1 + (size_t)sxl * 8 + hh);
            const float uv[4] = {u.x, u.y, u.z, u.w};
#pragma unroll
            for (int j = 0; j < 4; j++) {
                float e = __expf(leaky02(uv[j] + ad4[j]) - mh4[j]);
                ws4[j] += e;
                sAl[w][hh + j][e16] = e;
            }
        }
        __syncwarp();
#pragma unroll
        for (int e0 = 0; e0 < 32; e0 += 4) {
            const int edge = e0 + ew;
            const int   sy = sSrc[w][edge];
            const float al = sAl[w][g8][edge];
            uint4 hv = *(const uint4*)(g_h1 + (size_t)sy * C1 + g8 * 8);
            float2 p0 = __half22float2(*(const __half2*)&hv.x);
            float2 p1 = __half22float2(*(const __half2*)&hv.y);
            float2 p2 = __half22float2(*(const __half2*)&hv.z);
            float2 p3 = __half22float2(*(const __half2*)&hv.w);
            a[0] += p0.x * al; a[1] += p0.y * al;
            a[2] += p1.x * al; a[3] += p1.y * al;
            a[4] += p2.x * al; a[5] += p2.y * al;
            a[6] += p3.x * al; a[7] += p3.y * al;
        }
        __syncwarp();
    }

    const int r = end - chunk;
    if (r > 0) {
        int i = chunk + lane;
        sSrc[w][lane] = (i < end) ? g_srcs[i] : gw;
        __syncwarp();
#pragma unroll
        for (int sub = 0; sub < 2; sub++) {
            const int e16 = sub * 16 + (lane >> 1);
            const bool valid = e16 < r;
            const int sxl = sSrc[w][e16];
            float4 u = *(const float4*)(g_as1 + (size_t)sxl * 8 + hh);
            const float uv[4] = {u.x, u.y, u.z, u.w};
#pragma unroll
            for (int j = 0; j < 4; j++) {
                float e = valid ? __expf(leaky02(uv[j] + ad4[j]) - mh4[j]) : 0.f;
                ws4[j] += e;
                sAl[w][hh + j][e16] = e;
            }
        }
        __syncwarp();
        if (r <= 16) {
#pragma unroll
            for (int e0 = 0; e0 < 16; e0 += 4) {
                const int edge = e0 + ew;
                const int   sy = sSrc[w][edge];
                const float al = sAl[w][g8][edge];
                uint4 hv = *(const uint4*)(g_h1 + (size_t)sy * C1 + g8 * 8);
                float2 p0 = __half22float2(*(const __half2*)&hv.x);
                float2 p1 = __half22float2(*(const __half2*)&hv.y);
                float2 p2 = __half22float2(*(const __half2*)&hv.z);
                float2 p3 = __half22float2(*(const __half2*)&hv.w);
                a[0] += p0.x * al; a[1] += p0.y * al;
                a[2] += p1.x * al; a[3] += p1.y * al;
                a[4] += p2.x * al; a[5] += p2.y * al;
                a[6] += p3.x * al; a[7] += p3.y * al;
            }
        } else {
#pragma unroll
            for (int e0 = 0; e0 < 32; e0 += 4) {
                const int edge = e0 + ew;
                const int   sy = sSrc[w][edge];
                const float al = sAl[w][g8][edge];
                uint4 hv = *(const uint4*)(g_h1 + (size_t)sy * C1 + g8 * 8);
                float2 p0 = __half22float2(*(const __half2*)&hv.x);
                float2 p1 = __half22float2(*(const __half2*)&hv.y);
                float2 p2 = __half22float2(*(const __half2*)&hv.z);
                float2 p3 = __half22float2(*(const __half2*)&hv.w);
                a[0] += p0.x * al; a[1] += p0.y * al;
                a[2] += p1.x * al; a[3] += p1.y * al;
                a[4] += p2.x * al; a[5] += p2.y * al;
                a[6] += p3.x * al; a[7] += p3.y * al;
            }
        }
        __syncwarp();
    }

#pragma unroll
    for (int o = 2; o <= 16; o <<= 1)
#pragma unroll
        for (int j = 0; j < 4; j++)
            ws4[j] += __shfl_xor_sync(0xffffffffu, ws4[j], o);

#pragma unroll
    for (int k = 0; k < 8; k++) {
        a[k] += __shfl_xor_sync(0xffffffffu, a[k], 8);
        a[k] += __shfl_xor_sync(0xffffffffu, a[k], 16);
    }

    float se[4], so[4];
#pragma unroll
    for (int j = 0; j < 4; j++) {
        se[j] = __shfl_sync(0xffffffffu, ws4[j], 0);
        so[j] = __shfl_sync(0xffffffffu, ws4[j], 1);
    }

    if (lane < 8) {
        const int h = lane;
        float wsh = (h < 4) ? se[h] : so[h - 4];
        const float rsh = 1.0f / wsh;
        float4 b0 = *(const float4*)(b1 + h * 8);
        float4 b1v = *(const float4*)(b1 + h * 8 + 4);
        const float bb[8] = {b0.x, b0.y, b0.z, b0.w, b1v.x, b1v.y, b1v.z, b1v.w};
        float o[8];
#pragma unroll
        for (int k = 0; k < 8; k++) {
            float v = a[k] * rsh + bb[k];
            o[k] = (v > 0.f) ? v : (__expf(v) - 1.0f);
        }
        *(float4*)(g_hact + (size_t)gw * C1 + h * 8)     = make_float4(o[0], o[1], o[2], o[3]);
        *(float4*)(g_hact + (size_t)gw * C1 + h * 8 + 4) = make_float4(o[4], o[5], o[6], o[7]);
    }
}

// ---------------- layer2 GEMM + attn coefs + fused max ----------------
__global__ void gemm2_attn_k(const float* __restrict__ W2,
                             const float* __restrict__ asrc2,
                             const float* __restrict__ adst2) {
    __shared__ float Xs[16 * 64];
    __shared__ float Ws[64 * 16];
    __shared__ unsigned sM2;
    const int tid = threadIdx.x;
    const int n0  = blockIdx.x * 16;
    if (tid == 0) sM2 = ENC_NEG_INF;

    ((float4*)Ws)[tid] = ((const float4*)W2)[tid];
    {
        int row = tid >> 4;
        float4 v = make_float4(0.f, 0.f, 0.f, 0.f);
        if (n0 + row < N_NODES)
            v = ((const float4*)(g_hact + (size_t)n0 * C1))[tid];
        ((float4*)Xs)[tid] = v;
    }
    __syncthreads();

    const int r = tid >> 4, c = tid & 15;
    float acc = 0.f;
#pragma unroll
    for (int k = 0; k < 64; k++) acc += Xs[r * 64 + k] * Ws[k * 16 + c];
    const int n = n0 + r;
    if (n < N_NODES) g_h2[(size_t)n * NCLS + c] = __float2half_rn(acc);

    float vs = acc * asrc2[c];
    float vd = acc * adst2[c];
#pragma unroll
    for (int off = 8; off; off >>= 1) {
        vs += __shfl_xor_sync(0xffffffffu, vs, off);
        vd += __shfl_xor_sync(0xffffffffu, vd, off);
    }
    if (c == 0) {
        if (n < N_NODES) {
            g_as2[n] = vs;
            g_ad2[n] = vd;
            atomicMax(&sM2, fenc(vs));
        }
    }
    __syncthreads();
    if (tid == 0) atomicMax(&g_gmax2, sM2);
}

// ---------------- layer2 aggregate: 4ch x 8-edge-way gather ----------------
__global__ void agg2_k(const float* __restrict__ b2, float* __restrict__ out) {
    const int gw   = (blockIdx.x * blockDim.x + threadIdx.x) >> 5;
    const int lane = threadIdx.x & 31;
    const int w    = threadIdx.x >> 5;
    __shared__ float sAl [8][32];
    __shared__ int   sSrc[8][32];
    if (gw >= N_NODES) return;
    const int beg = g_rowptr[gw], end = g_rowptr[gw + 1];
    const float adn = g_ad2[gw];
    const float mh  = leaky02(fdec(g_gmax2) + adn);

    const int c4 = (lane & 3) * 4;
    const int ew = lane >> 2;
    float acc[4] = {0.f, 0.f, 0.f, 0.f};
    float ws = 0.f;

    int chunk = beg;
    for (; chunk + 32 <= end; chunk += 32) {
        const int sx = g_srcs[chunk + lane];
        const float e = __expf(leaky02(g_as2[sx] + adn) - mh);
        ws += e;
        sSrc[w][lane] = sx;
        sAl [w][lane] = e;
        __syncwarp();
#pragma unroll
        for (int e0 = 0; e0 < 32; e0 += 8) {
            const int edge = e0 + ew;
            const int   sy = sSrc[w][edge];
            const float al = sAl[w][edge];
            uint2 hv = *(const uint2*)(g_h2 + (size_t)sy * NCLS + c4);
            float2 p0 = __half22float2(*(const __half2*)&hv.x);
            float2 p1 = __half22float2(*(const __half2*)&hv.y);
            acc[0] += p0.x * al; acc[1] += p0.y * al;
            acc[2] += p1.x * al; acc[3] += p1.y * al;
        }
        __syncwarp();
    }

    const int r = end - chunk;
    if (r > 0) {
        int i = chunk + lane;
        int sx = gw;
        float e = 0.f;
        if (i < end) {
            sx = g_srcs[i];
            e  = __expf(leaky02(g_as2[sx] + adn) - mh);
            ws += e;
        }
        sSrc[w][lane] = sx;
        sAl [w][lane] = e;
        __syncwarp();
        if (r <= 8) {
            const int edge = ew;
            const int   sy = sSrc[w][edge];
            const float al = sAl[w][edge];
            uint2 hv = *(const uint2*)(g_h2 + (size_t)sy * NCLS + c4);
            float2 p0 = __half22float2(*(const __half2*)&hv.x);
            float2 p1 = __half22float2(*(const __half2*)&hv.y);
            acc[0] += p0.x * al; acc[1] += p0.y * al;
            acc[2] += p1.x * al; acc[3] += p1.y * al;
        } else if (r <= 16) {
#pragma unroll
            for (int e0 = 0; e0 < 16; e0 += 8) {
                const int edge = e0 + ew;
                const int   sy = sSrc[w][edge];
                const float al = sAl[w][edge];
                uint2 hv = *(const uint2*)(g_h2 + (size_t)sy * NCLS + c4);
                float2 p0 = __half22float2(*(const __half2*)&hv.x);
                float2 p1 = __half22float2(*(const __half2*)&hv.y);
                acc[0] += p0.x * al; acc[1] += p0.y * al;
                acc[2] += p1.x * al; acc[3] += p1.y * al;
            }
        } else {
#pragma unroll
            for (int e0 = 0; e0 < 32; e0 += 8) {
                const int edge = e0 + ew;
                const int   sy = sSrc[w][edge];
                const float al = sAl[w][edge];
                uint2 hv = *(const uint2*)(g_h2 + (size_t)sy * NCLS + c4);
                float2 p0 = __half22float2(*(const __half2*)&hv.x);
                float2 p1 = __half22float2(*(const __half2*)&hv.y);
                acc[0] += p0.x * al; acc[1] += p0.y * al;
                acc[2] += p1.x * al; acc[3] += p1.y * al;
            }
        }
        __syncwarp();
    }

#pragma unroll
    for (int o = 16; o; o >>= 1)
        ws += __shfl_xor_sync(0xffffffffu, ws, o);
    const float rs = 1.0f / ws;

#pragma unroll
    for (int k = 0; k < 4; k++) {
        acc[k] += __shfl_xor_sync(0xffffffffu, acc[k], 4);
        acc[k] += __shfl_xor_sync(0xffffffffu, acc[k], 8);
        acc[k] += __shfl_xor_sync(0xffffffffu, acc[k], 16);
    }

    if (lane < 4) {
        float4 bb = *(const float4*)(b2 + c4);
        *(float4*)(out + (size_t)gw * NCLS + c4) =
            make_float4(acc[0] * rs + bb.x, acc[1] * rs + bb.y,
                        acc[2] * rs + bb.z, acc[3] * rs + bb.w);
    }
}

// ---------------- streams for graph fork/join ----------------
static cudaStream_t g_s1;
static cudaEvent_t  g_ev0, g_ev1;
namespace {
struct StreamInit {
    StreamInit() {
        cudaStreamCreateWithFlags(&g_s1, cudaStreamNonBlocking);
        cudaEventCreateWithFlags(&g_ev0, cudaEventDisableTiming);
        cudaEventCreateWithFlags(&g_ev1, cudaEventDisableTiming);
    }
};
static StreamInit g_streaminit;
}

// ---------------- launch ----------------
extern "C" void kernel_launch(void* const* d_in, const int* in_sizes, int n_in,
                              void* d_out, int out_size) {
    const float* x    = (const float*)d_in[0];
    const void*  ei   = d_in[1];
    const float* W1   = (const float*)d_in[2];
    const float* as1w = (const float*)d_in[3];
    const float* ad1w = (const float*)d_in[4];
    const float* b1   = (const float*)d_in[5];
    const float* W2   = (const float*)d_in[6];
    const float* as2w = (const float*)d_in[7];
    const float* ad2w = (const float*)d_in[8];
    const float* b2   = (const float*)d_in[9];
    float* out = (float*)d_out;

    const int smem = SM_EL * 2;   // 61440 bytes
    cudaFuncSetAttribute(gemm1_k, cudaFuncAttributeMaxDynamicSharedMemorySize, smem);

    probe_k<<<1, 256>>>(ei);                                          // launch 0
    wsplit_k<<<(F_IN * C1 + 255) / 256, 256>>>(W1);                   // launch 1

    cudaEventRecord(g_ev0, 0);
    cudaStreamWaitEvent(g_s1, g_ev0, 0);

    initcnt_k<<<(N_NODES + 255) / 256, 256, 0, g_s1>>>();             // launch 2

    gemm1_k<<<(N_NODES + GM_M - 1) / GM_M, 256, smem>>>(x, as1w, ad1w);  // launch 3 (ncu slot)

    count_k<<<(N_EDGES / 2 + 255) / 256, 256, 0, g_s1>>>(ei);
    scan1_k<<<NB1024, 1024, 0, g_s1>>>();
    scan2_k<<<1, 128, 0, g_s1>>>();
    scan3_selfloop_k<<<NB1024, 1024, 0, g_s1>>>();
    scatter_k<<<(N_EDGES / 2 + 255) / 256, 256, 0, g_s1>>>(ei);
    cudaEventRecord(g_ev1, g_s1);

    cudaStreamWaitEvent(0, g_ev1, 0);

    agg1_k<<<(N_NODES + 7) / 8, 256>>>(b1);
    gemm2_attn_k<<<(N_NODES + 15) / 16, 256>>>(W2, as2w, ad2w);
    agg2_k<<<(N_NODES + 7) / 8, 256>>>(b2, out);
}